// round 8
// baseline (speedup 1.0000x reference)
#include <cuda_runtime.h>
#include <cuda_bf16.h>
#include <cstdint>

#define Bn 128
#define Tn 256
#define NHID 1024
#define NIN 128
#define NOUT 64
#define KTOT 1152
#define NCTA 128
#define THREADS 512
#define JGN 32          // j-groups
#define JSL 32          // j per CTA

// output layout: hidden_list [128][256][1024] ++ output_list [128][256][64] ++ h_final [128][1024]
#define OUT_HID 0
#define OUT_OUT 33554432
#define OUT_HF  35651584

// -------- device scratch --------
__device__ float g_act[2][NHID * Bn];              // tanh(h) [k][b], double buffered
__device__ float g_xT[Tn * NIN * Bn];              // x transposed [t][i][b]
__device__ float g_outpart[2][JGN * Bn * NOUT];    // out partials [jg][b*64+o]
__device__ unsigned g_arrive4[128];                // per-bg barrier counters (stride 32)
__device__ unsigned g_release4[128];

typedef unsigned long long ull;

__device__ __forceinline__ ull pack2(float x) {
    ull r; asm("mov.b64 %0, {%1, %1};" : "=l"(r) : "f"(x)); return r;
}
__device__ __forceinline__ void fma2(ull& c, ull a, ull b) {
    asm("fma.rn.f32x2 %0, %1, %2, %0;" : "+l"(c) : "l"(a), "l"(b));
}
__device__ __forceinline__ float2 unpack2(ull v) {
    float2 f; asm("mov.b64 {%0, %1}, %2;" : "=f"(f.x), "=f"(f.y) : "l"(v)); return f;
}
__device__ __forceinline__ void cpasync16(uint32_t dst, const float* src) {
    asm volatile("cp.async.cg.shared.global [%0], [%1], 16;" :: "r"(dst), "l"(src));
}
__device__ __forceinline__ void cpcommit() { asm volatile("cp.async.commit_group;"); }
template<int N> __device__ __forceinline__ void cpwait() {
    asm volatile("cp.async.wait_group %0;" :: "n"(N));
}

// fast exact-formula tanh: 1 - 2/(exp(2x)+1) via MUFU
__device__ __forceinline__ float fast_tanh(float x) {
    float e;
    asm("ex2.approx.f32 %0, %1;" : "=f"(e) : "f"(x * 2.8853900817779268f));
    float r;
    asm("rcp.approx.f32 %0, %1;" : "=f"(r) : "f"(e + 1.0f));
    return __fmaf_rn(-2.0f, r, 1.0f);
}

// -------- x transpose: g_xT[t][i][b] = input_signal[b][t][i] --------
__global__ void xT_kernel(const float* __restrict__ in) {
    __shared__ float s[128][33];
    int t = blockIdx.x >> 2, ig = blockIdx.x & 3;
    for (int idx = threadIdx.x; idx < 128 * 32; idx += 256) {
        int b = idx >> 5, ii = idx & 31;
        s[b][ii] = in[b * (Tn * NIN) + t * NIN + ig * 32 + ii];
    }
    __syncthreads();
    for (int idx = threadIdx.x; idx < 4096; idx += 256) {
        int ii = idx >> 7, b = idx & 127;
        g_xT[t * (NIN * Bn) + (ig * 32 + ii) * Bn + b] = s[b][ii];
    }
}

// -------- smem layout (float offsets) --------
#define SM_W    0                       // [1152][32] weights ([k][j])
#define SM_ACT  (SM_W + KTOT * 32)      // act_w[16][3][256] private rings (red aliases)
#define SM_WO   (SM_ACT + 16 * 768)     // [32][64] w_out slice
#define SM_HB   (SM_WO + 2048)          // h staged [2][b][j]  [2][32][36]
#define SM_TJ   (SM_HB + 2 * 32 * 36)   // tanh(h) [j][b]   [32][36]
#define SM_FLOATS (SM_TJ + 32 * 36)
#define SMEM_BYTES (SM_FLOATS * 4)

__global__ void __launch_bounds__(THREADS, 1)
rnn_main(const float* __restrict__ hidden,
         const float* __restrict__ w_in,
         const float* __restrict__ w_hh,
         const float* __restrict__ w_b,
         const float* __restrict__ w_out,
         const float* __restrict__ alpha,
         const float* __restrict__ noise,
         const int* __restrict__ ptp,
         float* __restrict__ out)
{
    extern __shared__ float sm[];
    float* w_s   = sm + SM_W;
    float* act_s = sm + SM_ACT;
    float* red   = act_s;                 // alias: [8][32][36] = 9216 <= 12288 floats
    float* wo_s  = sm + SM_WO;
    float* hbb   = sm + SM_HB;            // [2][32][36]
    float* tj    = sm + SM_TJ;

    const int tid = threadIdx.x;
    const int cta = blockIdx.x;
    const int jg = cta & 31, bg = cta >> 5;
    const int jbase = jg * JSL, bbase = bg * 32;

    const int w   = tid >> 5;       // warp 0..15 : owns rows w*8..w*8+7 per chunk
    const int lid = tid & 31;
    const int bq  = lid & 7;        // -> 4 b at b0
    const int jq  = lid >> 3;       // -> 8 j at j0
    const int b0  = bq * 4;
    const int j0  = jq * 8;

    // ---- load weight slices into smem [k][32j] (once) ----
    {
        int jj = tid >> 4;          // 0..31
        int kk = tid & 15;          // 0..15
        const float* wr = w_hh + (size_t)(jbase + jj) * NHID;
        for (int k = kk; k < NHID; k += 16)
            w_s[k * 32 + jj] = wr[k];
        const float* wi = w_in + (size_t)(jbase + jj) * NIN;
        for (int i = kk; i < NIN; i += 16)
            w_s[(NHID + i) * 32 + jj] = wi[i];
    }
    for (int idx = tid; idx < JSL * 64; idx += THREADS) {
        int jj = idx >> 6, o = idx & 63;
        wo_s[jj * 64 + o] = w_out[o * NHID + jbase + jj];
    }

    // ---- per-thread h ownership: bloc = tid>>4, j = jp, jp+1 ----
    const int bloc = tid >> 4;
    const int jp = (tid & 15) * 2;
    const int bown = bbase + bloc;

    float2 al2 = *(const float2*)&alpha[jbase + jp];
    float2 bi2 = *(const float2*)&w_b[jbase + jp];
    float2 ns2 = make_float2(0.05f * sqrtf(al2.x), 0.05f * sqrtf(al2.y));
    const int pt = *ptp;

    float2 hv = *(const float2*)&hidden[(size_t)bown * NHID + jbase + jp];
    float h0 = hv.x, h1 = hv.y;

    // initial act buffer 0 = tanh(hidden), layout [k][b]
    g_act[0][(jbase + jp) * Bn + bown]     = fast_tanh(h0);
    g_act[0][(jbase + jp + 1) * Bn + bown] = fast_tanh(h1);

    // per-bg grid barrier (32 CTAs; dependency graph closed within bg group)
    unsigned bar_t = 0;
    if (tid == 0) bar_t = *((volatile unsigned*)&g_release4[bg * 32]);

#define GRIDBAR() do {                                                        \
        __threadfence();                                                      \
        __syncthreads();                                                      \
        if (tid == 0) {                                                       \
            bar_t += 32u;                                                     \
            unsigned a_ = atomicAdd(&g_arrive4[bg * 32], 1u) + 1u;            \
            if (a_ == bar_t) { atomicExch(&g_release4[bg * 32], bar_t); }     \
            else { while ((int)(*((volatile unsigned*)&g_release4[bg * 32]) - bar_t) < 0) {} } \
        }                                                                     \
        __syncthreads();                                                      \
    } while (0)

    // warp-private act ring: act_w[w][3][256]
    const uint32_t actw_u = (uint32_t)__cvta_generic_to_shared(act_s) + (uint32_t)(w * 768 * 4);
    const float* actw = act_s + w * 768;
    const int srow = lid >> 2;              // staging row 0..7
    const int scol = (lid & 3) * 8;         // staging col (8 floats = 2x16B)

    // stage warp-own rows of one k-chunk (given base [128][Bn]) into ring slot SLOT
#define WSTAGE(BASE, SLOT) do {                                               \
        const float* _s = (BASE) + (w * 8 + srow) * Bn + bbase + scol;        \
        uint32_t _d = actw_u + (uint32_t)(((SLOT) * 256 + srow * 32 + scol) * 4); \
        cpasync16(_d,      _s);                                               \
        cpasync16(_d + 16, _s + 4);                                           \
        cpcommit();                                                           \
    } while (0)

    // pre-stage item0 of step 0 (x chunk) into slot 0 — x needs no barrier
    WSTAGE(g_xT, 0);

    GRIDBAR();   // g_act[0] visible

    for (int t = 0; t < Tn; t++) {
        const float* asrc = g_act[t & 1];
        const float* hbp = hbb + ((t + 1) & 1) * (32 * 36);   // prev step's h
        const float* hbc = hbb + (t & 1) * (32 * 36);         // this step's h (written in epilogue)

        // prologue: stage item1 (= act chunk 0) into slot 1
        WSTAGE(asrc, 1);

        // ======== deferred work from step t-1 (overlaps GEMM warps) ========
        if (t > 1 && lid < 4) {
            // reduce out(t-2): 64 elems spread over 16 warps x 4 lanes
            int e = cta * 64 + w * 4 + lid;
            const float* src = g_outpart[t & 1];   // (t-2)&1 == t&1
            float s = 0.f;
            #pragma unroll
            for (int r = 0; r < JGN; r++) s += __ldcg(src + r * (Bn * NOUT) + e);
            out[OUT_OUT + cta * (Tn * NOUT) + (t - 2) * NOUT + (w * 4 + lid)] = s;
        }
        if (t > 0) {
            // hidden_list STG for t-1 (all 512 threads, float2 each)
            {
                int rw = tid >> 4, q = (tid & 15) * 2;
                float2 v = *(const float2*)(hbp + rw * 36 + q);
                *(float2*)&out[OUT_HID + (size_t)(bbase + rw) * (Tn * NHID)
                               + (size_t)(t - 1) * NHID + jbase + q] = v;
            }
            // out partial GEMM for t-1: [32b x 64o], K = 32
            {
                const int br = tid >> 4;
                const int o0 = (tid & 15) * 4;
                float oa0 = 0.f, oa1 = 0.f, oa2 = 0.f, oa3 = 0.f;
                #pragma unroll
                for (int j = 0; j < JSL; j++) {
                    float a = hbp[br * 36 + j];
                    float4 w4 = *(const float4*)(wo_s + j * 64 + o0);
                    oa0 += a * w4.x; oa1 += a * w4.y; oa2 += a * w4.z; oa3 += a * w4.w;
                }
                float* op = g_outpart[(t - 1) & 1] + jg * (Bn * NOUT);
                *(float4*)&op[(bbase + br) * 64 + o0] = make_float4(oa0, oa1, oa2, oa3);
            }
        }
        // ===================================================================

        ull acc[4][4];
        #pragma unroll
        for (int i = 0; i < 4; i++)
            #pragma unroll
            for (int j = 0; j < 4; j++) acc[i][j] = 0;

        // ---- GEMM: item order [x-chunk(8), act chunks 0..7]; slots n%3 ----
        #pragma unroll 1
        for (int n = 0; n < 9; n++) {
            if (n <= 6) {
                // stage item n+2 = act chunk n+1
                WSTAGE(asrc + (n + 1) * 128 * Bn, (n + 2) % 3);
                cpwait<2>();
            } else if (n == 7) {
                cpwait<1>();
            } else {
                cpwait<0>();
            }
            __syncwarp();

            const int kc = (n == 0) ? 8 : (n - 1);   // k-chunk index for weights
            const float* abk = actw + (n % 3) * 256 + b0;
            const float* wbk = w_s + (kc * 128 + w * 8) * 32 + j0;
            #pragma unroll
            for (int i = 0; i < 8; i++) {
                float4 av = *(const float4*)(abk + i * 32);
                ulonglong2 w01 = *(const ulonglong2*)(wbk + i * 32);
                ulonglong2 w23 = *(const ulonglong2*)(wbk + i * 32 + 4);
                ull a0 = pack2(av.x), a1 = pack2(av.y);
                ull a2 = pack2(av.z), a3 = pack2(av.w);
                fma2(acc[0][0], a0, w01.x); fma2(acc[0][1], a0, w01.y);
                fma2(acc[0][2], a0, w23.x); fma2(acc[0][3], a0, w23.y);
                fma2(acc[1][0], a1, w01.x); fma2(acc[1][1], a1, w01.y);
                fma2(acc[1][2], a1, w23.x); fma2(acc[1][3], a1, w23.y);
                fma2(acc[2][0], a2, w01.x); fma2(acc[2][1], a2, w01.y);
                fma2(acc[2][2], a2, w23.x); fma2(acc[2][3], a2, w23.y);
                fma2(acc[3][0], a3, w01.x); fma2(acc[3][1], a3, w01.y);
                fma2(acc[3][2], a3, w23.x); fma2(acc[3][3], a3, w23.y);
            }
        }
        __syncthreads();   // all warps done with act rings (red aliases them)

        // ---- 16-way k-split reduce, deterministic ----
        if (w >= 8) {
            float* rd = red + (w - 8) * (32 * 36);
            #pragma unroll
            for (int bb = 0; bb < 4; bb++) {
                float2 v0 = unpack2(acc[bb][0]);
                float2 v1 = unpack2(acc[bb][1]);
                float2 v2 = unpack2(acc[bb][2]);
                float2 v3 = unpack2(acc[bb][3]);
                *(float4*)(rd + (b0 + bb) * 36 + j0)     = make_float4(v0.x, v0.y, v1.x, v1.y);
                *(float4*)(rd + (b0 + bb) * 36 + j0 + 4) = make_float4(v2.x, v2.y, v3.x, v3.y);
            }
        }
        __syncthreads();
        if (w < 8) {
            float* rd = red + w * (32 * 36);
            #pragma unroll
            for (int bb = 0; bb < 4; bb++) {
                float4 p0 = *(const float4*)(rd + (b0 + bb) * 36 + j0);
                float4 p1 = *(const float4*)(rd + (b0 + bb) * 36 + j0 + 4);
                float2 v0 = unpack2(acc[bb][0]);
                float2 v1 = unpack2(acc[bb][1]);
                float2 v2 = unpack2(acc[bb][2]);
                float2 v3 = unpack2(acc[bb][3]);
                *(float4*)(rd + (b0 + bb) * 36 + j0) =
                    make_float4(v0.x + p0.x, v0.y + p0.y, v1.x + p0.z, v1.y + p0.w);
                *(float4*)(rd + (b0 + bb) * 36 + j0 + 4) =
                    make_float4(v2.x + p1.x, v2.y + p1.y, v3.x + p1.z, v3.y + p1.w);
            }
        }
        __syncthreads();

        // ---- 8-way reduce + h update (thread owns bloc, jp..jp+1) ----
        {
            float s0 = bi2.x, s1 = bi2.y;
            #pragma unroll
            for (int g = 0; g < 8; g++) {
                float2 v = *(const float2*)(red + g * (32 * 36) + bloc * 36 + jp);
                s0 += v.x; s1 += v.y;
            }
            h0 = (1.f - al2.x) * h0 + al2.x * s0;
            h1 = (1.f - al2.y) * h1 + al2.y * s1;
            if (t == pt) {
                float2 n = *(const float2*)&noise[(size_t)bown * NHID + jbase + jp];
                h0 += n.x * ns2.x;
                h1 += n.y * ns2.y;
            }
        }

        // stage hb (this step's buffer) and tj
        *(float2*)&((float*)hbc)[bloc * 36 + jp] = make_float2(h0, h1);
        tj[(jp)     * 36 + bloc] = fast_tanh(h0);
        tj[(jp + 1) * 36 + bloc] = fast_tanh(h1);
        __syncthreads();     // also: all red reads complete -> ring slot 0 reusable

        // next act buffer write (all 512 threads, float2 each; row = local j)
        {
            int rw = tid >> 4, q = (tid & 15) * 2;
            float2 a = *(const float2*)(tj + rw * 36 + q);
            *(float2*)&g_act[(t + 1) & 1][(jbase + rw) * Bn + bbase + q] = a;
        }

        // pre-stage next step's item0 (x chunk) into ring slot 0 — no barrier needed
        if (t + 1 < Tn)
            WSTAGE(g_xT + (t + 1) * (NIN * Bn), 0);

        GRIDBAR();
    }

    // ======== drain: deferred work for t = 255 ========
    {
        const float* hbp = hbb + ((Tn - 1) & 1) * (32 * 36);
        // reduce out(254)  (parity (Tn-2)&1 = 0)
        if (lid < 4) {
            int e = cta * 64 + w * 4 + lid;
            const float* src = g_outpart[(Tn - 2) & 1];
            float s = 0.f;
            #pragma unroll
            for (int r = 0; r < JGN; r++) s += __ldcg(src + r * (Bn * NOUT) + e);
            out[OUT_OUT + cta * (Tn * NOUT) + (Tn - 2) * NOUT + (w * 4 + lid)] = s;
        }
        // hidden_list STG for 255 + h_final
        {
            int rw = tid >> 4, q = (tid & 15) * 2;
            float2 v = *(const float2*)(hbp + rw * 36 + q);
            *(float2*)&out[OUT_HID + (size_t)(bbase + rw) * (Tn * NHID)
                           + (size_t)(Tn - 1) * NHID + jbase + q] = v;
            *(float2*)&out[OUT_HF + (size_t)(bbase + rw) * NHID + jbase + q] = v;
        }
        // out partial GEMM for 255
        {
            const int br = tid >> 4;
            const int o0 = (tid & 15) * 4;
            float oa0 = 0.f, oa1 = 0.f, oa2 = 0.f, oa3 = 0.f;
            #pragma unroll
            for (int j = 0; j < JSL; j++) {
                float a = hbp[br * 36 + j];
                float4 w4 = *(const float4*)(wo_s + j * 64 + o0);
                oa0 += a * w4.x; oa1 += a * w4.y; oa2 += a * w4.z; oa3 += a * w4.w;
            }
            float* op = g_outpart[(Tn - 1) & 1] + jg * (Bn * NOUT);
            *(float4*)&op[(bbase + br) * 64 + o0] = make_float4(oa0, oa1, oa2, oa3);
        }
    }
    GRIDBAR();
    // final reduce out(255)
    if (lid < 4) {
        int e = cta * 64 + w * 4 + lid;
        const float* src = g_outpart[(Tn - 1) & 1];
        float s = 0.f;
        #pragma unroll
        for (int r = 0; r < JGN; r++) s += __ldcg(src + r * (Bn * NOUT) + e);
        out[OUT_OUT + cta * (Tn * NOUT) + (Tn - 1) * NOUT + (w * 4 + lid)] = s;
    }
#undef GRIDBAR
#undef WSTAGE
}

// -------- launcher --------
extern "C" void kernel_launch(void* const* d_in, const int* in_sizes, int n_in,
                              void* d_out, int out_size)
{
    const float* input_signal = (const float*)d_in[0];
    const float* hidden       = (const float*)d_in[1];
    const float* w_in_w       = (const float*)d_in[2];
    const float* w_hh_w       = (const float*)d_in[3];
    const float* w_hh_b       = (const float*)d_in[4];
    const float* w_out_w      = (const float*)d_in[5];
    const float* alpha        = (const float*)d_in[6];
    const float* noise_raw    = (const float*)d_in[7];
    const int*   pt           = (const int*)d_in[8];
    float* out = (float*)d_out;

    cudaFuncSetAttribute(rnn_main, cudaFuncAttributeMaxDynamicSharedMemorySize, SMEM_BYTES);

    xT_kernel<<<1024, 256>>>(input_signal);
    rnn_main<<<NCTA, THREADS, SMEM_BYTES>>>(hidden, w_in_w, w_hh_w, w_hh_b,
                                            w_out_w, alpha, noise_raw, pt, out);
}